// round 5
// baseline (speedup 1.0000x reference)
#include <cuda_runtime.h>
#include <cuda_bf16.h>
#include <math.h>

#define BB 2
#define TT 1024
#define DD 1024
#define NH 16
#define HDIM 64
#define NL 6
#define VV 50257
#define FF (4*DD)
#define LNEPS 1e-5f
#define BT (BB*TT)

typedef __nv_bfloat16 bf16;

// ---------------- scratch ----------------
__device__ float g_x [BT*DD];
__device__ float g_sc[(long)BB*NH*TT*TT];

__device__ bf16 g_hh[BT*DD], g_hl[BT*DD];
__device__ bf16 g_qh[BT*DD], g_ql[BT*DD];
__device__ bf16 g_kh[BT*DD], g_kl[BT*DD];
__device__ bf16 g_vh[BT*DD], g_vl[BT*DD];
__device__ bf16 g_ah[BT*DD], g_al[BT*DD];
__device__ bf16 g_fh[BT*FF], g_fl[BT*FF];
__device__ bf16 g_ph[(long)BB*NH*TT*TT], g_pl[(long)BB*NH*TT*TT];

__device__ bf16 g_wqh[NL*DD*DD], g_wql[NL*DD*DD];
__device__ bf16 g_wkh[NL*DD*DD], g_wkl[NL*DD*DD];
__device__ bf16 g_wvh[NL*DD*DD], g_wvl[NL*DD*DD];
__device__ bf16 g_woh[NL*DD*DD], g_wol[NL*DD*DD];
__device__ bf16 g_w1h[(long)NL*DD*FF], g_w1l[(long)NL*DD*FF];
__device__ bf16 g_w2h[(long)NL*DD*FF], g_w2l[(long)NL*DD*FF];
__device__ bf16 g_tkh[(long)VV*DD], g_tkl[(long)VV*DD];

// ---------------- helpers ----------------
__device__ __forceinline__ float warpSum(float v){
#pragma unroll
  for (int o=16;o;o>>=1) v += __shfl_xor_sync(0xffffffffu, v, o);
  return v;
}
__device__ __forceinline__ float warpMax(float v){
#pragma unroll
  for (int o=16;o;o>>=1) v = fmaxf(v, __shfl_xor_sync(0xffffffffu, v, o));
  return v;
}
__device__ float blockSum(float v){
  __shared__ float sh[8];
  __syncthreads();
  int lane = threadIdx.x & 31, w = threadIdx.x >> 5;
  v = warpSum(v);
  if (lane == 0) sh[w] = v;
  __syncthreads();
  if (w == 0){
    v = (lane < (int)(blockDim.x>>5)) ? sh[lane] : 0.f;
    v = warpSum(v);
    if (lane == 0) sh[0] = v;
  }
  __syncthreads();
  return sh[0];
}
__device__ float blockMax(float v){
  __shared__ float sh[8];
  __syncthreads();
  int lane = threadIdx.x & 31, w = threadIdx.x >> 5;
  v = warpMax(v);
  if (lane == 0) sh[w] = v;
  __syncthreads();
  if (w == 0){
    v = (lane < (int)(blockDim.x>>5)) ? sh[lane] : -3.0e38f;
    v = warpMax(v);
    if (lane == 0) sh[0] = v;
  }
  __syncthreads();
  return sh[0];
}

__device__ __forceinline__ void splitstore(bf16* H, bf16* L, long idx, float v){
  bf16 h = __float2bfloat16_rn(v);
  H[idx] = h;
  L[idx] = __float2bfloat16_rn(v - __bfloat162float(h));
}

// ---------------- weight split (fp32 -> bf16 hi/lo planes) ----------------
__global__ void split_kernel(const float4* __restrict__ src,
                             uint2* __restrict__ hi, uint2* __restrict__ lo, long n4){
  long i = (long)blockIdx.x*blockDim.x + threadIdx.x;
  long stride = (long)gridDim.x*blockDim.x;
  for (; i < n4; i += stride){
    float4 v = src[i];
    bf16 h0=__float2bfloat16_rn(v.x), h1=__float2bfloat16_rn(v.y);
    bf16 h2=__float2bfloat16_rn(v.z), h3=__float2bfloat16_rn(v.w);
    bf16 l0=__float2bfloat16_rn(v.x-__bfloat162float(h0));
    bf16 l1=__float2bfloat16_rn(v.y-__bfloat162float(h1));
    bf16 l2=__float2bfloat16_rn(v.z-__bfloat162float(h2));
    bf16 l3=__float2bfloat16_rn(v.w-__bfloat162float(h3));
    uint2 H, L;
    H.x = (unsigned)__bfloat16_as_ushort(h0) | ((unsigned)__bfloat16_as_ushort(h1)<<16);
    H.y = (unsigned)__bfloat16_as_ushort(h2) | ((unsigned)__bfloat16_as_ushort(h3)<<16);
    L.x = (unsigned)__bfloat16_as_ushort(l0) | ((unsigned)__bfloat16_as_ushort(l1)<<16);
    L.y = (unsigned)__bfloat16_as_ushort(l2) | ((unsigned)__bfloat16_as_ushort(l3)<<16);
    hi[i] = H; lo[i] = L;
  }
}

// ---------------- embed ----------------
__global__ void embed_kernel(const int* __restrict__ idx,
                             const float* __restrict__ tokW,
                             const float* __restrict__ posW,
                             float* __restrict__ x){
  int i = blockIdx.x;
  int t = i % TT;
  long tok = idx[i];
  const float* tw = tokW + tok*DD;
  const float* pw = posW + (long)t*DD;
  float* xr = x + (long)i*DD;
  for (int d = threadIdx.x; d < DD; d += blockDim.x)
    xr[d] = tw[d] + pw[d];
}

// ---------------- layernorm -> bf16 planes ----------------
__global__ void ln_kernel(const float* __restrict__ x,
                          bf16* __restrict__ yh, bf16* __restrict__ yl,
                          const float* __restrict__ g, const float* __restrict__ b){
  int row = blockIdx.x;
  const float* xr = x + (long)row*DD;
  float s = 0.f, ss = 0.f;
  for (int d = threadIdx.x; d < DD; d += blockDim.x){
    float v = xr[d]; s += v; ss += v*v;
  }
  s = blockSum(s);
  ss = blockSum(ss);
  float mean = s * (1.f/DD);
  float var  = ss * (1.f/DD) - mean*mean;
  float rstd = rsqrtf(var + LNEPS);
  long base = (long)row*DD;
  for (int d = threadIdx.x; d < DD; d += blockDim.x){
    float v = (xr[d] - mean)*rstd*g[d] + b[d];
    splitstore(yh, yl, base + d, v);
  }
}

// ---------------- causal softmax: fp32 scores -> bf16 plane probs ----------------
__global__ void softmax_kernel(const float* __restrict__ sc,
                               bf16* __restrict__ ph, bf16* __restrict__ pl){
  int row = blockIdx.x;
  int bh  = blockIdx.y;
  long base = ((long)bh*TT + row)*TT;
  const float* s = sc + base;
  int n = row + 1;
  float m = -3.0e38f;
  for (int j = threadIdx.x; j < n; j += blockDim.x) m = fmaxf(m, s[j]);
  m = blockMax(m);
  float sum = 0.f;
  for (int j = threadIdx.x; j < n; j += blockDim.x) sum += expf(s[j] - m);
  sum = blockSum(sum);
  float inv = 1.f / sum;
  bf16 z = __float2bfloat16(0.f);
  for (int j = threadIdx.x; j < TT; j += blockDim.x){
    if (j < n) splitstore(ph, pl, base + j, expf(s[j]-m)*inv);
    else { ph[base+j] = z; pl[base+j] = z; }
  }
}

// ---------------- mma / ldsm / cp.async primitives ----------------
__device__ __forceinline__ void ldsm4(unsigned r[4], const void* p){
  unsigned a = (unsigned)__cvta_generic_to_shared(p);
  asm volatile("ldmatrix.sync.aligned.m8n8.x4.shared.b16 {%0,%1,%2,%3}, [%4];"
    : "=r"(r[0]),"=r"(r[1]),"=r"(r[2]),"=r"(r[3]) : "r"(a));
}
__device__ __forceinline__ void ldsm4t(unsigned &r0, unsigned &r1, unsigned &r2, unsigned &r3, const void* p){
  unsigned a = (unsigned)__cvta_generic_to_shared(p);
  asm volatile("ldmatrix.sync.aligned.m8n8.x4.trans.shared.b16 {%0,%1,%2,%3}, [%4];"
    : "=r"(r0),"=r"(r1),"=r"(r2),"=r"(r3) : "r"(a));
}
__device__ __forceinline__ void mma16816(float d[4], const unsigned a[4], const unsigned b[2]){
  asm volatile("mma.sync.aligned.m16n8k16.row.col.f32.bf16.bf16.f32 "
    "{%0,%1,%2,%3}, {%4,%5,%6,%7}, {%8,%9}, {%0,%1,%2,%3};"
    : "+f"(d[0]),"+f"(d[1]),"+f"(d[2]),"+f"(d[3])
    : "r"(a[0]),"r"(a[1]),"r"(a[2]),"r"(a[3]), "r"(b[0]),"r"(b[1]));
}
__device__ __forceinline__ void cpa16(void* dst, const void* src){
  unsigned d = (unsigned)__cvta_generic_to_shared(dst);
  asm volatile("cp.async.cg.shared.global [%0], [%1], 16;" :: "r"(d), "l"(src));
}
__device__ __forceinline__ void cpa_commit(){ asm volatile("cp.async.commit_group;"); }
__device__ __forceinline__ void cpa_wait1(){ asm volatile("cp.async.wait_group 1;"); }
__device__ __forceinline__ void cpa_wait0(){ asm volatile("cp.async.wait_group 0;"); }

// ---------------- planes GEMM ----------------
// C[M,N] = epi( alpha * (Ah+Al)[M,K] @ (Bh+Bl) )
// TRANSB=false: B planes stored [K,N]; true: [N,K].
// EPI: 0 -> C fp32 (alpha applied); 1 -> planes Ch/Cl; 2 -> C fp32 += acc+bias; 3 -> gelu(acc+bias) planes.
// CMODE: 0 none; 1 skip tiles with n0 >= m0+128 (causal scores); 2 limit K to m0+128 (causal P@V).
// BM=128, BK=16, 256 threads, 3-stage cp.async.
template<int BN, bool TRANSB, int EPI, int CMODE>
__global__ void __launch_bounds__(256,1)
pgemm(int M, int N, int K, float alpha,
      const bf16* __restrict__ Ah, const bf16* __restrict__ Al, int lda, long sA1, long sA2,
      const bf16* __restrict__ Bh, const bf16* __restrict__ Bl, int ldb, long sB1, long sB2,
      float* __restrict__ C, bf16* __restrict__ Ch, bf16* __restrict__ Cl, int ldc, long sC1, long sC2,
      const float* __restrict__ bias)
{
  constexpr int WGN = BN/32;            // 4 or 2
  constexpr int WGM = 8/WGN;            // 2 or 4
  constexpr int WROWS = 128/WGM;        // 64 or 32
  constexpr int MI = WROWS/16;          // 4 or 2
  constexpr int BR = TRANSB ? 128 : 16;
  constexpr int BC = TRANSB ? 16 : BN;

  __shared__ bf16 As[3][2][128][16];
  __shared__ bf16 Bs[3][2][BR][BC];

  const int m0 = blockIdx.y * 128;
  const int n0 = blockIdx.x * BN;
  if (CMODE == 1 && n0 >= m0 + 128) return;

  int z  = blockIdx.z;
  int zb = z / NH, zh = z % NH;
  Ah += (long)zb*sA1 + (long)zh*sA2;  Al += (long)zb*sA1 + (long)zh*sA2;
  Bh += (long)zb*sB1 + (long)zh*sB2;  Bl += (long)zb*sB1 + (long)zh*sB2;
  long coff = (long)zb*sC1 + (long)zh*sC2;
  if (EPI == 0 || EPI == 2) C += coff; else { Ch += coff; Cl += coff; }

  const int tid = threadIdx.x;
  const int warp = tid >> 5, lane = tid & 31;
  const int wm = warp / WGN, wn = warp % WGN;
  const int lrow = lane & 15;
  const int lch  = lane >> 4;          // 0/1 chunk

  int Keff = (CMODE == 2) ? (m0 + 128 < K ? m0 + 128 : K) : K;
  const int NT = Keff >> 4;

  // ---- stage loader ----
#define LOAD_STAGE(st, kt) { \
    { int p = tid>>7, row = tid&127; \
      const bf16* s_ = (p ? Al : Ah) + (long)(m0+row)*lda + (kt); \
      int sw = (row>>2)&1; \
      cpa16(&As[st][p][row][(0^sw)<<3], s_); \
      cpa16(&As[st][p][row][(1^sw)<<3], s_+8); } \
    if (TRANSB) { int p = tid>>7, row = tid&127; \
      int sw = (row>>2)&1; \
      if (n0+row < N) { \
        const bf16* s_ = (p ? Bl : Bh) + (long)(n0+row)*ldb + (kt); \
        cpa16(&Bs[st][p][row][(0^sw)<<3], s_); \
        cpa16(&Bs[st][p][row][(1^sw)<<3], s_+8); \
      } else { \
        *(uint4*)&Bs[st][p][row][(0^sw)<<3] = make_uint4(0,0,0,0); \
        *(uint4*)&Bs[st][p][row][(1^sw)<<3] = make_uint4(0,0,0,0); \
      } \
    } else if (BN == 128) { \
      int p = tid>>7, rem = tid&127, row = rem>>3, c0 = (rem&7)*2; \
      const bf16* s_ = (p ? Bl : Bh) + (long)((kt)+row)*ldb + n0 + c0*8; \
      cpa16(&Bs[st][p][row][(c0^(row&7))<<3], s_); \
      cpa16(&Bs[st][p][row][((c0+1)^(row&7))<<3], s_+8); \
    } else { \
      int p = tid>>7, rem = tid&127, row = rem>>3, c0 = rem&7; \
      const bf16* s_ = (p ? Bl : Bh) + (long)((kt)+row)*ldb + n0 + c0*8; \
      cpa16(&Bs[st][p][row][(c0^(row&7))<<3], s_); \
    } \
    cpa_commit(); }

  float acc[MI][4][4];
#pragma unroll
  for (int i=0;i<MI;i++)
#pragma unroll
    for (int j=0;j<4;j++)
#pragma unroll
      for (int r=0;r<4;r++) acc[i][j][r]=0.f;

  LOAD_STAGE(0, 0);
  LOAD_STAGE(1, 16);

  for (int it = 0; it < NT; ++it) {
    if (it + 1 < NT) cpa_wait1(); else cpa_wait0();
    __syncthreads();
    int nxt = it + 2;
    if (nxt < NT) { int stn = nxt % 3; LOAD_STAGE(stn, nxt<<4); }
    const int buf = it % 3;

    unsigned Af[MI][4], Alf[MI][4], Bf[4][2], Blf[4][2];
#pragma unroll
    for (int mi=0; mi<MI; mi++){
      int row = wm*WROWS + mi*16 + lrow;
      int off = ((lch ^ ((row>>2)&1)) << 3);
      ldsm4(Af[mi],  &As[buf][0][row][off]);
      ldsm4(Alf[mi], &As[buf][1][row][off]);
    }
    if (TRANSB) {
#pragma unroll
      for (int np=0; np<2; np++){
        int nl = wn*32 + np*16 + (lane&7) + ((lane>>4)<<3);
        int ch = (lane>>3)&1;
        int off = ((ch ^ ((nl>>2)&1)) << 3);
        unsigned t0[4], t1[4];
        ldsm4(t0, &Bs[buf][0][nl][off]);
        ldsm4(t1, &Bs[buf][1][nl][off]);
        Bf[2*np][0]=t0[0]; Bf[2*np][1]=t0[1]; Bf[2*np+1][0]=t0[2]; Bf[2*np+1][1]=t0[3];
        Blf[2*np][0]=t1[0]; Blf[2*np][1]=t1[1]; Blf[2*np+1][0]=t1[2]; Blf[2*np+1][1]=t1[3];
      }
    } else {
#pragma unroll
      for (int np=0; np<2; np++){
        int n  = wn*32 + np*16 + (lch<<3);
        int off = (((n>>3) ^ (lrow&7)) << 3);
        ldsm4t(Bf[2*np][0],Bf[2*np][1],Bf[2*np+1][0],Bf[2*np+1][1],  &Bs[buf][0][lrow][off]);
        ldsm4t(Blf[2*np][0],Blf[2*np][1],Blf[2*np+1][0],Blf[2*np+1][1], &Bs[buf][1][lrow][off]);
      }
    }
#pragma unroll
    for (int mi=0; mi<MI; mi++)
#pragma unroll
      for (int ni=0; ni<4; ni++){
        mma16816(acc[mi][ni], Af[mi],  Bf[ni]);
        mma16816(acc[mi][ni], Alf[mi], Bf[ni]);
        mma16816(acc[mi][ni], Af[mi],  Blf[ni]);
      }
    __syncthreads();
  }

  // ---- epilogue ----
  const int rb = m0 + wm*WROWS + (lane >> 2);
  const int cb = n0 + wn*32 + 2*(lane & 3);
#pragma unroll
  for (int mi=0; mi<MI; mi++){
#pragma unroll
    for (int ni=0; ni<4; ni++){
      int c0 = cb + ni*8;
#pragma unroll
      for (int r=0; r<4; r++){
        int row = rb + mi*16 + ((r>>1)<<3);
        int col = c0 + (r&1);
        if (col >= N) continue;
        float v = acc[mi][ni][r];
        long idx = (long)row*ldc + col;
        if (EPI == 0) C[idx] = alpha * v;
        else if (EPI == 1) splitstore(Ch, Cl, idx, v);
        else if (EPI == 2) C[idx] = C[idx] + v + bias[col];
        else { v += bias[col]; v = 0.5f*v*(1.f + erff(v*0.70710678118654752f)); splitstore(Ch, Cl, idx, v); }
      }
    }
  }
#undef LOAD_STAGE
}

// ---------------- host ----------------
extern "C" void kernel_launch(void* const* d_in, const int* in_sizes, int n_in,
                              void* d_out, int out_size) {
  const int*   idx  = (const int*  )d_in[0];
  const float* tokW = (const float*)d_in[1];
  const float* posW = (const float*)d_in[2];
  const float* ln1g = (const float*)d_in[3];
  const float* ln1b = (const float*)d_in[4];
  const float* Wq   = (const float*)d_in[5];
  const float* Wk   = (const float*)d_in[6];
  const float* Wv   = (const float*)d_in[7];
  const float* Wo   = (const float*)d_in[8];
  const float* bo   = (const float*)d_in[9];
  const float* ln2g = (const float*)d_in[10];
  const float* ln2b = (const float*)d_in[11];
  const float* W1   = (const float*)d_in[12];
  const float* b1   = (const float*)d_in[13];
  const float* W2   = (const float*)d_in[14];
  const float* b2   = (const float*)d_in[15];
  const float* lnfg = (const float*)d_in[16];
  const float* lnfb = (const float*)d_in[17];
  float* out = (float*)d_out;

  float *x, *sc;
  bf16 *hh,*hl,*qh,*ql,*kh,*kl,*vh,*vl,*ah,*al,*fh,*fl,*ph,*pl;
  bf16 *wqh,*wql,*wkh,*wkl,*wvh,*wvl,*woh,*wol,*w1h,*w1l,*w2h,*w2l,*tkh,*tkl;
  cudaGetSymbolAddress((void**)&x, g_x);  cudaGetSymbolAddress((void**)&sc, g_sc);
  cudaGetSymbolAddress((void**)&hh, g_hh); cudaGetSymbolAddress((void**)&hl, g_hl);
  cudaGetSymbolAddress((void**)&qh, g_qh); cudaGetSymbolAddress((void**)&ql, g_ql);
  cudaGetSymbolAddress((void**)&kh, g_kh); cudaGetSymbolAddress((void**)&kl, g_kl);
  cudaGetSymbolAddress((void**)&vh, g_vh); cudaGetSymbolAddress((void**)&vl, g_vl);
  cudaGetSymbolAddress((void**)&ah, g_ah); cudaGetSymbolAddress((void**)&al, g_al);
  cudaGetSymbolAddress((void**)&fh, g_fh); cudaGetSymbolAddress((void**)&fl, g_fl);
  cudaGetSymbolAddress((void**)&ph, g_ph); cudaGetSymbolAddress((void**)&pl, g_pl);
  cudaGetSymbolAddress((void**)&wqh, g_wqh); cudaGetSymbolAddress((void**)&wql, g_wql);
  cudaGetSymbolAddress((void**)&wkh, g_wkh); cudaGetSymbolAddress((void**)&wkl, g_wkl);
  cudaGetSymbolAddress((void**)&wvh, g_wvh); cudaGetSymbolAddress((void**)&wvl, g_wvl);
  cudaGetSymbolAddress((void**)&woh, g_woh); cudaGetSymbolAddress((void**)&wol, g_wol);
  cudaGetSymbolAddress((void**)&w1h, g_w1h); cudaGetSymbolAddress((void**)&w1l, g_w1l);
  cudaGetSymbolAddress((void**)&w2h, g_w2h); cudaGetSymbolAddress((void**)&w2l, g_w2l);
  cudaGetSymbolAddress((void**)&tkh, g_tkh); cudaGetSymbolAddress((void**)&tkl, g_tkl);

  // ---- weight preconversion ----
  long nW  = (long)NL*DD*DD/4;
  long nW1 = (long)NL*DD*FF/4;
  long nTk = (long)VV*DD/4;
  split_kernel<<<2048,256>>>((const float4*)Wq, (uint2*)wqh, (uint2*)wql, nW);
  split_kernel<<<2048,256>>>((const float4*)Wk, (uint2*)wkh, (uint2*)wkl, nW);
  split_kernel<<<2048,256>>>((const float4*)Wv, (uint2*)wvh, (uint2*)wvl, nW);
  split_kernel<<<2048,256>>>((const float4*)Wo, (uint2*)woh, (uint2*)wol, nW);
  split_kernel<<<4096,256>>>((const float4*)W1, (uint2*)w1h, (uint2*)w1l, nW1);
  split_kernel<<<4096,256>>>((const float4*)W2, (uint2*)w2h, (uint2*)w2l, nW1);
  split_kernel<<<8192,256>>>((const float4*)tokW, (uint2*)tkh, (uint2*)tkl, nTk);

  embed_kernel<<<BT, 256>>>(idx, tokW, posW, x);

  const dim3 gDD (DD/128,  BT/128, 1);
  const dim3 gFF (FF/128,  BT/128, 1);
  const dim3 gSC (TT/128,  TT/128, BB*NH);
  const dim3 gAV (1,       TT/128, BB*NH);
  const dim3 gLM ((VV+127)/128, BT/128, 1);
  const long sDD2 = (long)DD*DD;
  const long sDF  = (long)DD*FF;

  for (int l = 0; l < NL; l++) {
    long lDD = (long)l*DD, lF = (long)l*FF;

    ln_kernel<<<BT,256>>>(x, hh, hl, ln1g + lDD, ln1b + lDD);

    pgemm<128,false,1,0><<<gDD,256>>>(BT, DD, DD, 1.f,
        hh, hl, DD,0,0,  wqh + l*sDD2, wql + l*sDD2, DD,0,0,
        nullptr, qh, ql, DD,0,0, nullptr);
    pgemm<128,false,1,0><<<gDD,256>>>(BT, DD, DD, 1.f,
        hh, hl, DD,0,0,  wkh + l*sDD2, wkl + l*sDD2, DD,0,0,
        nullptr, kh, kl, DD,0,0, nullptr);
    pgemm<128,false,1,0><<<gDD,256>>>(BT, DD, DD, 1.f,
        hh, hl, DD,0,0,  wvh + l*sDD2, wvl + l*sDD2, DD,0,0,
        nullptr, vh, vl, DD,0,0, nullptr);

    // scores = 0.125 * q @ k^T   (causal tile skip)
    pgemm<128,true,0,1><<<gSC,256>>>(TT, TT, HDIM, 0.125f,
        qh, ql, DD, (long)TT*DD, HDIM,
        kh, kl, DD, (long)TT*DD, HDIM,
        sc, nullptr, nullptr, TT, (long)NH*TT*TT, (long)TT*TT, nullptr);

    softmax_kernel<<<dim3(TT, BB*NH), 256>>>(sc, ph, pl);

    // att = P @ v   (causal K limit, BN=64)
    pgemm<64,false,1,2><<<gAV,256>>>(TT, HDIM, TT, 1.f,
        ph, pl, TT, (long)NH*TT*TT, (long)TT*TT,
        vh, vl, DD, (long)TT*DD, HDIM,
        nullptr, ah, al, DD, (long)TT*DD, HDIM, nullptr);

    // x += att @ Wo + bo
    pgemm<128,false,2,0><<<gDD,256>>>(BT, DD, DD, 1.f,
        ah, al, DD,0,0,  woh + l*sDD2, wol + l*sDD2, DD,0,0,
        x, nullptr, nullptr, DD,0,0, bo + lDD);

    ln_kernel<<<BT,256>>>(x, hh, hl, ln2g + lDD, ln2b + lDD);

    // ff = gelu(h @ W1 + b1)
    pgemm<128,false,3,0><<<gFF,256>>>(BT, FF, DD, 1.f,
        hh, hl, DD,0,0,  w1h + l*sDF, w1l + l*sDF, FF,0,0,
        nullptr, fh, fl, FF,0,0, b1 + lF);

    // x += ff @ W2 + b2
    pgemm<128,false,2,0><<<gDD,256>>>(BT, DD, FF, 1.f,
        fh, fl, FF,0,0,  w2h + l*sDF, w2l + l*sDF, DD,0,0,
        x, nullptr, nullptr, DD,0,0, b2 + lDD);
  }

  ln_kernel<<<BT,256>>>(x, hh, hl, lnfg, lnfb);

  // logits = h @ tokW^T
  pgemm<128,true,0,0><<<gLM,256>>>(BT, VV, DD, 1.f,
      hh, hl, DD,0,0,  tkh, tkl, DD,0,0,
      out, nullptr, nullptr, VV,0,0, nullptr);
}

// round 6
// speedup vs baseline: 1.2885x; 1.2885x over previous
#include <cuda_runtime.h>
#include <cuda_bf16.h>
#include <math.h>

#define BB 2
#define TT 1024
#define DD 1024
#define NH 16
#define HDIM 64
#define NL 6
#define VV 50257
#define FF (4*DD)
#define LNEPS 1e-5f
#define BT (BB*TT)

typedef __nv_bfloat16 bf16;

// ---------------- scratch ----------------
__device__ float g_x  [BT*DD];
__device__ float g_h  [BT*DD];
__device__ float g_qkv[BT*3*DD];
__device__ float g_att[BT*DD];
__device__ float g_ff [BT*FF];
__device__ float g_sc [(long)BB*NH*TT*TT];
__device__ float g_wc [(long)NL*DD*3*DD];   // concatenated Wq|Wk|Wv per layer

// ---------------- reductions ----------------
__device__ __forceinline__ float warpSum(float v){
#pragma unroll
  for (int o=16;o;o>>=1) v += __shfl_xor_sync(0xffffffffu, v, o);
  return v;
}
__device__ __forceinline__ float warpMax(float v){
#pragma unroll
  for (int o=16;o;o>>=1) v = fmaxf(v, __shfl_xor_sync(0xffffffffu, v, o));
  return v;
}
__device__ float blockSum(float v){
  __shared__ float sh[8];
  __syncthreads();
  int lane = threadIdx.x & 31, w = threadIdx.x >> 5;
  v = warpSum(v);
  if (lane == 0) sh[w] = v;
  __syncthreads();
  if (w == 0){
    v = (lane < (int)(blockDim.x>>5)) ? sh[lane] : 0.f;
    v = warpSum(v);
    if (lane == 0) sh[0] = v;
  }
  __syncthreads();
  return sh[0];
}
__device__ float blockMax(float v){
  __shared__ float sh[8];
  __syncthreads();
  int lane = threadIdx.x & 31, w = threadIdx.x >> 5;
  v = warpMax(v);
  if (lane == 0) sh[w] = v;
  __syncthreads();
  if (w == 0){
    v = (lane < (int)(blockDim.x>>5)) ? sh[lane] : -3.0e38f;
    v = warpMax(v);
    if (lane == 0) sh[0] = v;
  }
  __syncthreads();
  return sh[0];
}

// ---------------- QKV weight concat ----------------
__global__ void concat_qkv(const float* __restrict__ Wq, const float* __restrict__ Wk,
                           const float* __restrict__ Wv, float* __restrict__ Wc){
  long n4 = (long)NL*DD*3*DD/4;
  for (long i = (long)blockIdx.x*blockDim.x + threadIdx.x; i < n4; i += (long)gridDim.x*blockDim.x){
    long e = i*4;
    long c = e % (3*DD);
    long r = (e / (3*DD)) % DD;
    long l = e / ((long)3*DD*DD);
    const float* src;
    if (c < DD)        src = Wq + ((l*DD + r)*DD + c);
    else if (c < 2*DD) src = Wk + ((l*DD + r)*DD + (c - DD));
    else               src = Wv + ((l*DD + r)*DD + (c - 2*DD));
    *(float4*)(Wc + e) = *(const float4*)src;
  }
}

// ---------------- embed ----------------
__global__ void embed_kernel(const int* __restrict__ idx,
                             const float* __restrict__ tokW,
                             const float* __restrict__ posW,
                             float* __restrict__ x){
  int i = blockIdx.x;
  int t = i % TT;
  long tok = idx[i];
  const float* tw = tokW + tok*DD;
  const float* pw = posW + (long)t*DD;
  float* xr = x + (long)i*DD;
  for (int d = threadIdx.x; d < DD; d += blockDim.x)
    xr[d] = tw[d] + pw[d];
}

// ---------------- layernorm ----------------
__global__ void ln_kernel(const float* __restrict__ x, float* __restrict__ y,
                          const float* __restrict__ g, const float* __restrict__ b){
  int row = blockIdx.x;
  const float* xr = x + (long)row*DD;
  float s = 0.f, ss = 0.f;
  for (int d = threadIdx.x; d < DD; d += blockDim.x){
    float v = xr[d]; s += v; ss += v*v;
  }
  s = blockSum(s);
  ss = blockSum(ss);
  float mean = s * (1.f/DD);
  float var  = ss * (1.f/DD) - mean*mean;
  float rstd = rsqrtf(var + LNEPS);
  float* yr = y + (long)row*DD;
  for (int d = threadIdx.x; d < DD; d += blockDim.x)
    yr[d] = (xr[d] - mean) * rstd * g[d] + b[d];
}

// ---------------- causal softmax (in place) ----------------
__global__ void softmax_kernel(float* __restrict__ sc){
  int row = blockIdx.x;
  int bh  = blockIdx.y;
  float* s = sc + ((long)bh*TT + row)*TT;
  int n = row + 1;
  float m = -3.0e38f;
  for (int j = threadIdx.x; j < n; j += blockDim.x) m = fmaxf(m, s[j]);
  m = blockMax(m);
  float sum = 0.f;
  for (int j = threadIdx.x; j < n; j += blockDim.x){
    float e = expf(s[j] - m);
    s[j] = e; sum += e;
  }
  sum = blockSum(sum);
  float inv = 1.f / sum;
  for (int j = threadIdx.x; j < TT; j += blockDim.x)
    s[j] = (j < n) ? s[j]*inv : 0.f;
}

// ---------------- mma primitives ----------------
__device__ __forceinline__ void split2(float x0, float x1, unsigned &h, unsigned &l){
  bf16 h0 = __float2bfloat16_rn(x0);
  bf16 h1 = __float2bfloat16_rn(x1);
  bf16 l0 = __float2bfloat16_rn(x0 - __bfloat162float(h0));
  bf16 l1 = __float2bfloat16_rn(x1 - __bfloat162float(h1));
  h = (unsigned)__bfloat16_as_ushort(h0) | ((unsigned)__bfloat16_as_ushort(h1) << 16);
  l = (unsigned)__bfloat16_as_ushort(l0) | ((unsigned)__bfloat16_as_ushort(l1) << 16);
}
__device__ __forceinline__ void ldsm4(unsigned r[4], const void* p){
  unsigned a = (unsigned)__cvta_generic_to_shared(p);
  asm volatile("ldmatrix.sync.aligned.m8n8.x4.shared.b16 {%0,%1,%2,%3}, [%4];"
    : "=r"(r[0]),"=r"(r[1]),"=r"(r[2]),"=r"(r[3]) : "r"(a));
}
__device__ __forceinline__ void ldsm4t(unsigned &r0, unsigned &r1, unsigned &r2, unsigned &r3, const void* p){
  unsigned a = (unsigned)__cvta_generic_to_shared(p);
  asm volatile("ldmatrix.sync.aligned.m8n8.x4.trans.shared.b16 {%0,%1,%2,%3}, [%4];"
    : "=r"(r0),"=r"(r1),"=r"(r2),"=r"(r3) : "r"(a));
}
__device__ __forceinline__ void mma16816(float d[4], const unsigned a[4], const unsigned b[2]){
  asm volatile("mma.sync.aligned.m16n8k16.row.col.f32.bf16.bf16.f32 "
    "{%0,%1,%2,%3}, {%4,%5,%6,%7}, {%8,%9}, {%0,%1,%2,%3};"
    : "+f"(d[0]),"+f"(d[1]),"+f"(d[2]),"+f"(d[3])
    : "r"(a[0]),"r"(a[1]),"r"(a[2]),"r"(a[3]), "r"(b[0]),"r"(b[1]));
}

// ---------------- bf16x3 tensor-core GEMM (fp32 in/out, split in-register) ----------------
// TRANSB=false: B [K,N]; true: B [N,K] (BN must be 128).
// EPI: 0 -> C = alpha*acc; 2 -> C += acc + bias; 3 -> C = gelu(acc+bias)
// CM: 0 none; 1 skip tile if n0 >= m0+128 (causal scores); 2 K limited to m0+128 (causal P@V)
// 256 threads. BM in {64,128}; BN in {64,128}. NN path requires N % BN == 0.
template<int BM,int BN,bool TRANSB,int EPI,int CM>
__global__ void __launch_bounds__(256,2)
bgemm(int M, int N, int K, float alpha,
      const float* __restrict__ A, int lda, long sA1, long sA2,
      const float* __restrict__ B, int ldb, long sB1, long sB2,
      float* __restrict__ C, int ldc, long sC1, long sC2,
      const float* __restrict__ bias)
{
  constexpr int WGN = (BN >= 128) ? 4 : 2;
  constexpr int WGM = 8 / WGN;
  constexpr int WROWS = BM / WGM;     // 64 or 32
  constexpr int MI = WROWS / 16;      // 4 or 2
  constexpr int BC = (BN == 128) ? 136 : 72;

  __shared__ bf16 As[2][2][BM][24];
  __shared__ bf16 Bs[2][2][16][BC];

  const int m0 = blockIdx.y * BM;
  const int n0 = blockIdx.x * BN;
  if (CM == 1 && n0 >= m0 + BM) return;

  int z  = blockIdx.z;
  int zb = z / NH, zh = z % NH;
  A += (long)zb*sA1 + (long)zh*sA2;
  B += (long)zb*sB1 + (long)zh*sB2;
  C += (long)zb*sC1 + (long)zh*sC2;

  const int tid = threadIdx.x;
  const int warp = tid >> 5, lane = tid & 31;
  const int wm = warp / WGN, wn = warp % WGN;
  const int lrow = lane & 15;
  const int lcol = (lane >> 4) << 3;

  // loader indices
  const int arow = tid >> 2;          // 0..63
  const int akc  = (tid & 3) << 2;
  const int bk   = tid >> 5;          // NN BN=128
  const int bc   = (tid & 31) << 2;
  const int bk2  = tid >> 4;          // NN BN=64: 0..15
  const int bc2  = (tid & 15) << 2;
  const int tn   = tid & 127;         // TT
  const int tkh  = (tid >> 7) << 3;

  float4 pA0, pA1, pB0, pB1;

#define PREF_A(kt) { \
    pA0 = *(const float4*)&A[(long)(m0+arow)*lda + (kt) + akc]; \
    if (BM == 128) pA1 = *(const float4*)&A[(long)(m0+arow+64)*lda + (kt) + akc]; }

#define STORE_A(bf) { \
    unsigned h_, l_; \
    split2(pA0.x,pA0.y,h_,l_); *(unsigned*)&As[bf][0][arow][akc]=h_;   *(unsigned*)&As[bf][1][arow][akc]=l_; \
    split2(pA0.z,pA0.w,h_,l_); *(unsigned*)&As[bf][0][arow][akc+2]=h_; *(unsigned*)&As[bf][1][arow][akc+2]=l_; \
    if (BM == 128) { \
      split2(pA1.x,pA1.y,h_,l_); *(unsigned*)&As[bf][0][arow+64][akc]=h_;   *(unsigned*)&As[bf][1][arow+64][akc]=l_; \
      split2(pA1.z,pA1.w,h_,l_); *(unsigned*)&As[bf][0][arow+64][akc+2]=h_; *(unsigned*)&As[bf][1][arow+64][akc+2]=l_; } }

#define PREF_B(kt) { \
    if (TRANSB) { \
      if (n0 + tn < N) { \
        pB0 = *(const float4*)&B[(long)(n0+tn)*ldb + (kt) + tkh]; \
        pB1 = *(const float4*)&B[(long)(n0+tn)*ldb + (kt) + tkh + 4]; \
      } else { pB0 = make_float4(0.f,0.f,0.f,0.f); pB1 = pB0; } \
    } else if (BN == 128) { \
      pB0 = *(const float4*)&B[(long)((kt)+bk)*ldb + n0 + bc]; \
      pB1 = *(const float4*)&B[(long)((kt)+bk+8)*ldb + n0 + bc]; \
    } else { \
      pB0 = *(const float4*)&B[(long)((kt)+bk2)*ldb + n0 + bc2]; \
    } }

#define STORE_B(bf) { \
    if (TRANSB) { \
      float v_[8] = {pB0.x,pB0.y,pB0.z,pB0.w,pB1.x,pB1.y,pB1.z,pB1.w}; \
      _Pragma("unroll") \
      for (int i_=0;i_<8;i_++){ \
        bf16 hh_ = __float2bfloat16_rn(v_[i_]); \
        Bs[bf][0][tkh+i_][tn] = hh_; \
        Bs[bf][1][tkh+i_][tn] = __float2bfloat16_rn(v_[i_] - __bfloat162float(hh_)); } \
    } else if (BN == 128) { \
      unsigned h_, l_; \
      split2(pB0.x,pB0.y,h_,l_); *(unsigned*)&Bs[bf][0][bk][bc]=h_;     *(unsigned*)&Bs[bf][1][bk][bc]=l_; \
      split2(pB0.z,pB0.w,h_,l_); *(unsigned*)&Bs[bf][0][bk][bc+2]=h_;   *(unsigned*)&Bs[bf][1][bk][bc+2]=l_; \
      split2(pB1.x,pB1.y,h_,l_); *(unsigned*)&Bs[bf][0][bk+8][bc]=h_;   *(unsigned*)&Bs[bf][1][bk+8][bc]=l_; \
      split2(pB1.z,pB1.w,h_,l_); *(unsigned*)&Bs[bf][0][bk+8][bc+2]=h_; *(unsigned*)&Bs[bf][1][bk+8][bc+2]=l_; \
    } else { \
      unsigned h_, l_; \
      split2(pB0.x,pB0.y,h_,l_); *(unsigned*)&Bs[bf][0][bk2][bc2]=h_;   *(unsigned*)&Bs[bf][1][bk2][bc2]=l_; \
      split2(pB0.z,pB0.w,h_,l_); *(unsigned*)&Bs[bf][0][bk2][bc2+2]=h_; *(unsigned*)&Bs[bf][1][bk2][bc2+2]=l_; } }

  float acc[MI][4][4];
#pragma unroll
  for (int i=0;i<MI;i++)
#pragma unroll
    for (int j=0;j<4;j++)
#pragma unroll
      for (int r=0;r<4;r++) acc[i][j][r]=0.f;

  int Keff = (CM == 2) ? ((m0 + BM < K) ? m0 + BM : K) : K;
  const int NT = Keff >> 4;

  PREF_A(0); PREF_B(0);
  STORE_A(0); STORE_B(0);
  __syncthreads();

  for (int it = 0; it < NT; ++it) {
    const int bf = it & 1;
    const bool more = (it + 1) < NT;
    if (more) { PREF_A((it+1)<<4); PREF_B((it+1)<<4); }

    unsigned Ah[MI][4], Al[MI][4], Bh[4][2], Bl[4][2];
#pragma unroll
    for (int mi=0; mi<MI; mi++){
      ldsm4(Ah[mi], &As[bf][0][wm*WROWS + mi*16 + lrow][lcol]);
      ldsm4(Al[mi], &As[bf][1][wm*WROWS + mi*16 + lrow][lcol]);
    }
#pragma unroll
    for (int np=0; np<2; np++){
      ldsm4t(Bh[2*np][0],Bh[2*np][1],Bh[2*np+1][0],Bh[2*np+1][1],
             &Bs[bf][0][lrow][wn*32 + np*16 + lcol]);
      ldsm4t(Bl[2*np][0],Bl[2*np][1],Bl[2*np+1][0],Bl[2*np+1][1],
             &Bs[bf][1][lrow][wn*32 + np*16 + lcol]);
    }
#pragma unroll
    for (int mi=0; mi<MI; mi++)
#pragma unroll
      for (int ni=0; ni<4; ni++){
        mma16816(acc[mi][ni], Ah[mi], Bh[ni]);
        mma16816(acc[mi][ni], Al[mi], Bh[ni]);
        mma16816(acc[mi][ni], Ah[mi], Bl[ni]);
      }

    if (more) { STORE_A(!bf); STORE_B(!bf); }
    __syncthreads();
  }

  // ---- epilogue ----
  const int rb = m0 + wm*WROWS + (lane >> 2);
  const int cb = n0 + wn*32 + 2*(lane & 3);
#pragma unroll
  for (int mi=0; mi<MI; mi++){
#pragma unroll
    for (int ni=0; ni<4; ni++){
      int c0 = cb + ni*8;
#pragma unroll
      for (int r=0; r<4; r++){
        int row = rb + mi*16 + ((r>>1)<<3);
        int col = c0 + (r&1);
        if (col >= N) continue;
        float v = acc[mi][ni][r];
        long idx = (long)row*ldc + col;
        if (EPI == 0) C[idx] = alpha * v;
        else if (EPI == 2) C[idx] = C[idx] + v + bias[col];
        else { v += bias[col]; C[idx] = 0.5f*v*(1.f + erff(v*0.70710678118654752f)); }
      }
    }
  }
#undef PREF_A
#undef STORE_A
#undef PREF_B
#undef STORE_B
}

// ---------------- host ----------------
extern "C" void kernel_launch(void* const* d_in, const int* in_sizes, int n_in,
                              void* d_out, int out_size) {
  const int*   idx  = (const int*  )d_in[0];
  const float* tokW = (const float*)d_in[1];
  const float* posW = (const float*)d_in[2];
  const float* ln1g = (const float*)d_in[3];
  const float* ln1b = (const float*)d_in[4];
  const float* Wq   = (const float*)d_in[5];
  const float* Wk   = (const float*)d_in[6];
  const float* Wv   = (const float*)d_in[7];
  const float* Wo   = (const float*)d_in[8];
  const float* bo   = (const float*)d_in[9];
  const float* ln2g = (const float*)d_in[10];
  const float* ln2b = (const float*)d_in[11];
  const float* W1   = (const float*)d_in[12];
  const float* b1   = (const float*)d_in[13];
  const float* W2   = (const float*)d_in[14];
  const float* b2   = (const float*)d_in[15];
  const float* lnfg = (const float*)d_in[16];
  const float* lnfb = (const float*)d_in[17];
  float* out = (float*)d_out;

  float *x,*h,*qkv,*att,*ff,*sc,*wc;
  cudaGetSymbolAddress((void**)&x,   g_x);
  cudaGetSymbolAddress((void**)&h,   g_h);
  cudaGetSymbolAddress((void**)&qkv, g_qkv);
  cudaGetSymbolAddress((void**)&att, g_att);
  cudaGetSymbolAddress((void**)&ff,  g_ff);
  cudaGetSymbolAddress((void**)&sc,  g_sc);
  cudaGetSymbolAddress((void**)&wc,  g_wc);

  concat_qkv<<<4096,256>>>(Wq, Wk, Wv, wc);
  embed_kernel<<<BT,256>>>(idx, tokW, posW, x);

  const dim3 gQKV(3*DD/128, BT/128, 1);        // 24 x 16 = 384
  const dim3 gD64(DD/128,   BT/64,  1);        // 8 x 32  = 256
  const dim3 gFF (FF/128,   BT/128, 1);        // 32 x 16 = 512
  const dim3 gSC (TT/128,   TT/128, BB*NH);    // 8 x 8 x 32 (~56% survive causal skip)
  const dim3 gAV (1,        TT/128, BB*NH);    // 1 x 8 x 32
  const dim3 gLM ((VV+127)/128, BT/128, 1);    // 393 x 16
  const long sD3 = (long)DD*3*DD;
  const long sDD2 = (long)DD*DD;
  const long sDF  = (long)DD*FF;

  for (int l = 0; l < NL; l++) {
    long lDD = (long)l*DD, lF = (long)l*FF;

    ln_kernel<<<BT,256>>>(x, h, ln1g + lDD, ln1b + lDD);

    // fused QKV:  qkv[BT, 3D] = h @ Wcat[l]
    bgemm<128,128,false,0,0><<<gQKV,256>>>(BT, 3*DD, DD, 1.f,
        h, DD,0,0,  wc + l*sD3, 3*DD,0,0,  qkv, 3*DD,0,0, nullptr);

    // scores = 0.125 * q @ k^T  (causal tile skip)
    bgemm<128,128,true,0,1><<<gSC,256>>>(TT, TT, HDIM, 0.125f,
        qkv,      3*DD, (long)TT*3*DD, HDIM,
        qkv + DD, 3*DD, (long)TT*3*DD, HDIM,
        sc, TT, (long)NH*TT*TT, (long)TT*TT, nullptr);

    softmax_kernel<<<dim3(TT, BB*NH), 256>>>(sc);

    // att = P @ v  (causal K limit)
    bgemm<128,64,false,0,2><<<gAV,256>>>(TT, HDIM, TT, 1.f,
        sc,         TT,   (long)NH*TT*TT, (long)TT*TT,
        qkv + 2*DD, 3*DD, (long)TT*3*DD,  HDIM,
        att, DD, (long)TT*DD, HDIM, nullptr);

    // x += att @ Wo + bo   (BM=64 -> 256 CTAs)
    bgemm<64,128,false,2,0><<<gD64,256>>>(BT, DD, DD, 1.f,
        att, DD,0,0,  Wo + l*sDD2, DD,0,0,  x, DD,0,0, bo + lDD);

    ln_kernel<<<BT,256>>>(x, h, ln2g + lDD, ln2b + lDD);

    // ff = gelu(h @ W1 + b1)
    bgemm<128,128,false,3,0><<<gFF,256>>>(BT, FF, DD, 1.f,
        h, DD,0,0,  W1 + l*sDF, FF,0,0,  ff, FF,0,0, b1 + lF);

    // x += ff @ W2 + b2   (BM=64 -> 256 CTAs)
    bgemm<64,128,false,2,0><<<gD64,256>>>(BT, DD, FF, 1.f,
        ff, FF,0,0,  W2 + l*sDF, DD,0,0,  x, DD,0,0, b2 + lDD);
  }

  ln_kernel<<<BT,256>>>(x, h, lnfg, lnfb);

  // logits = h @ tokW^T
  bgemm<128,128,true,0,0><<<gLM,256>>>(BT, VV, DD, 1.f,
      h, DD,0,0,  tokW, DD,0,0,  out, VV,0,0, nullptr);
}

// round 7
// speedup vs baseline: 1.3048x; 1.0127x over previous
#include <cuda_runtime.h>
#include <cuda_bf16.h>
#include <math.h>

#define BB 2
#define TT 1024
#define DD 1024
#define NH 16
#define HDIM 64
#define NL 6
#define VV 50257
#define FF (4*DD)
#define LNEPS 1e-5f
#define BT (BB*TT)

typedef __nv_bfloat16 bf16;

// ---------------- scratch ----------------
__device__ float g_x  [BT*DD];
__device__ float g_h  [BT*DD];
__device__ float g_qkv[BT*3*DD];
__device__ float g_att[BT*DD];
__device__ float g_ff [BT*FF];
__device__ float g_sc [(long)BB*NH*TT*TT];

// weight planes (bf16 hi/lo)
__device__ bf16 g_wch[(long)NL*DD*3*DD], g_wcl[(long)NL*DD*3*DD];
__device__ bf16 g_woh[(long)NL*DD*DD],   g_wol[(long)NL*DD*DD];
__device__ bf16 g_w1h[(long)NL*DD*FF],   g_w1l[(long)NL*DD*FF];
__device__ bf16 g_w2h[(long)NL*DD*FF],   g_w2l[(long)NL*DD*FF];
__device__ bf16 g_tkh[(long)VV*DD],      g_tkl[(long)VV*DD];

// ---------------- reductions ----------------
__device__ __forceinline__ float warpSum(float v){
#pragma unroll
  for (int o=16;o;o>>=1) v += __shfl_xor_sync(0xffffffffu, v, o);
  return v;
}
__device__ __forceinline__ float warpMax(float v){
#pragma unroll
  for (int o=16;o;o>>=1) v = fmaxf(v, __shfl_xor_sync(0xffffffffu, v, o));
  return v;
}
__device__ float blockSum(float v){
  __shared__ float sh[8];
  __syncthreads();
  int lane = threadIdx.x & 31, w = threadIdx.x >> 5;
  v = warpSum(v);
  if (lane == 0) sh[w] = v;
  __syncthreads();
  if (w == 0){
    v = (lane < (int)(blockDim.x>>5)) ? sh[lane] : 0.f;
    v = warpSum(v);
    if (lane == 0) sh[0] = v;
  }
  __syncthreads();
  return sh[0];
}
__device__ float blockMax(float v){
  __shared__ float sh[8];
  __syncthreads();
  int lane = threadIdx.x & 31, w = threadIdx.x >> 5;
  v = warpMax(v);
  if (lane == 0) sh[w] = v;
  __syncthreads();
  if (w == 0){
    v = (lane < (int)(blockDim.x>>5)) ? sh[lane] : -3.0e38f;
    v = warpMax(v);
    if (lane == 0) sh[0] = v;
  }
  __syncthreads();
  return sh[0];
}

// ---------------- weight split kernels ----------------
__device__ __forceinline__ void split4(float4 v, uint2 &H, uint2 &L){
  bf16 h0=__float2bfloat16_rn(v.x), h1=__float2bfloat16_rn(v.y);
  bf16 h2=__float2bfloat16_rn(v.z), h3=__float2bfloat16_rn(v.w);
  bf16 l0=__float2bfloat16_rn(v.x-__bfloat162float(h0));
  bf16 l1=__float2bfloat16_rn(v.y-__bfloat162float(h1));
  bf16 l2=__float2bfloat16_rn(v.z-__bfloat162float(h2));
  bf16 l3=__float2bfloat16_rn(v.w-__bfloat162float(h3));
  H.x = (unsigned)__bfloat16_as_ushort(h0) | ((unsigned)__bfloat16_as_ushort(h1)<<16);
  H.y = (unsigned)__bfloat16_as_ushort(h2) | ((unsigned)__bfloat16_as_ushort(h3)<<16);
  L.x = (unsigned)__bfloat16_as_ushort(l0) | ((unsigned)__bfloat16_as_ushort(l1)<<16);
  L.y = (unsigned)__bfloat16_as_ushort(l2) | ((unsigned)__bfloat16_as_ushort(l3)<<16);
}

__global__ void split_w(const float4* __restrict__ src,
                        uint2* __restrict__ hi, uint2* __restrict__ lo, long n4){
  long i = (long)blockIdx.x*blockDim.x + threadIdx.x;
  long stride = (long)gridDim.x*blockDim.x;
  for (; i < n4; i += stride){
    uint2 H, L;
    split4(src[i], H, L);
    hi[i] = H; lo[i] = L;
  }
}

// fused concat(Wq|Wk|Wv) + split into planes, layout [l][r][3*DD]
__global__ void split_qkv(const float* __restrict__ Wq, const float* __restrict__ Wk,
                          const float* __restrict__ Wv,
                          uint2* __restrict__ hi, uint2* __restrict__ lo){
  long n4 = (long)NL*DD*3*DD/4;
  for (long i = (long)blockIdx.x*blockDim.x + threadIdx.x; i < n4; i += (long)gridDim.x*blockDim.x){
    long e = i*4;
    long c = e % (3*DD);
    long r = (e / (3*DD)) % DD;
    long l = e / ((long)3*DD*DD);
    const float* src;
    if (c < DD)        src = Wq + ((l*DD + r)*DD + c);
    else if (c < 2*DD) src = Wk + ((l*DD + r)*DD + (c - DD));
    else               src = Wv + ((l*DD + r)*DD + (c - 2*DD));
    uint2 H, L;
    split4(*(const float4*)src, H, L);
    hi[i] = H; lo[i] = L;
  }
}

// ---------------- embed ----------------
__global__ void embed_kernel(const int* __restrict__ idx,
                             const float* __restrict__ tokW,
                             const float* __restrict__ posW,
                             float* __restrict__ x){
  int i = blockIdx.x;
  int t = i % TT;
  long tok = idx[i];
  const float* tw = tokW + tok*DD;
  const float* pw = posW + (long)t*DD;
  float* xr = x + (long)i*DD;
  for (int d = threadIdx.x; d < DD; d += blockDim.x)
    xr[d] = tw[d] + pw[d];
}

// ---------------- layernorm ----------------
__global__ void ln_kernel(const float* __restrict__ x, float* __restrict__ y,
                          const float* __restrict__ g, const float* __restrict__ b){
  int row = blockIdx.x;
  const float* xr = x + (long)row*DD;
  float s = 0.f, ss = 0.f;
  for (int d = threadIdx.x; d < DD; d += blockDim.x){
    float v = xr[d]; s += v; ss += v*v;
  }
  s = blockSum(s);
  ss = blockSum(ss);
  float mean = s * (1.f/DD);
  float var  = ss * (1.f/DD) - mean*mean;
  float rstd = rsqrtf(var + LNEPS);
  float* yr = y + (long)row*DD;
  for (int d = threadIdx.x; d < DD; d += blockDim.x)
    yr[d] = (xr[d] - mean) * rstd * g[d] + b[d];
}

// ---------------- causal softmax (in place) ----------------
__global__ void softmax_kernel(float* __restrict__ sc){
  int row = blockIdx.x;
  int bh  = blockIdx.y;
  float* s = sc + ((long)bh*TT + row)*TT;
  int n = row + 1;
  float m = -3.0e38f;
  for (int j = threadIdx.x; j < n; j += blockDim.x) m = fmaxf(m, s[j]);
  m = blockMax(m);
  float sum = 0.f;
  for (int j = threadIdx.x; j < n; j += blockDim.x){
    float e = expf(s[j] - m);
    s[j] = e; sum += e;
  }
  sum = blockSum(sum);
  float inv = 1.f / sum;
  for (int j = threadIdx.x; j < TT; j += blockDim.x)
    s[j] = (j < n) ? s[j]*inv : 0.f;
}

// ---------------- mma primitives ----------------
__device__ __forceinline__ void split2(float x0, float x1, unsigned &h, unsigned &l){
  bf16 h0 = __float2bfloat16_rn(x0);
  bf16 h1 = __float2bfloat16_rn(x1);
  bf16 l0 = __float2bfloat16_rn(x0 - __bfloat162float(h0));
  bf16 l1 = __float2bfloat16_rn(x1 - __bfloat162float(h1));
  h = (unsigned)__bfloat16_as_ushort(h0) | ((unsigned)__bfloat16_as_ushort(h1) << 16);
  l = (unsigned)__bfloat16_as_ushort(l0) | ((unsigned)__bfloat16_as_ushort(l1) << 16);
}
__device__ __forceinline__ void ldsm4(unsigned r[4], const void* p){
  unsigned a = (unsigned)__cvta_generic_to_shared(p);
  asm volatile("ldmatrix.sync.aligned.m8n8.x4.shared.b16 {%0,%1,%2,%3}, [%4];"
    : "=r"(r[0]),"=r"(r[1]),"=r"(r[2]),"=r"(r[3]) : "r"(a));
}
__device__ __forceinline__ void ldsm4t(unsigned &r0, unsigned &r1, unsigned &r2, unsigned &r3, const void* p){
  unsigned a = (unsigned)__cvta_generic_to_shared(p);
  asm volatile("ldmatrix.sync.aligned.m8n8.x4.trans.shared.b16 {%0,%1,%2,%3}, [%4];"
    : "=r"(r0),"=r"(r1),"=r"(r2),"=r"(r3) : "r"(a));
}
__device__ __forceinline__ void mma16816(float d[4], const unsigned a[4], const unsigned b[2]){
  asm volatile("mma.sync.aligned.m16n8k16.row.col.f32.bf16.bf16.f32 "
    "{%0,%1,%2,%3}, {%4,%5,%6,%7}, {%8,%9}, {%0,%1,%2,%3};"
    : "+f"(d[0]),"+f"(d[1]),"+f"(d[2]),"+f"(d[3])
    : "r"(a[0]),"r"(a[1]),"r"(a[2]),"r"(a[3]), "r"(b[0]),"r"(b[1]));
}

// ---------------- bf16x3 tensor-core GEMM ----------------
// A: fp32, split in-register. B: fp32 (PLB=false, split in-register) or
// preconverted bf16 hi/lo planes (PLB=true, straight copies into smem).
// TRANSB=false: B [K,N]; true: B [N,K] (BN must be 128).
// EPI: 0 -> C = alpha*acc; 2 -> C += acc + bias; 3 -> C = gelu(acc+bias)
// CM: 0 none; 1 skip tile if n0 >= m0+BM (causal scores); 2 K limited to m0+BM (causal P@V)
// 256 threads. BM in {64,128}; BN in {64,128}. NN path requires N % BN == 0.
template<int BM,int BN,bool TRANSB,bool PLB,int EPI,int CM>
__global__ void __launch_bounds__(256,2)
bgemm(int M, int N, int K, float alpha,
      const float* __restrict__ A, int lda, long sA1, long sA2,
      const float* __restrict__ B, const bf16* __restrict__ Bph, const bf16* __restrict__ Bpl,
      int ldb, long sB1, long sB2,
      float* __restrict__ C, int ldc, long sC1, long sC2,
      const float* __restrict__ bias)
{
  constexpr int WGN = (BN >= 128) ? 4 : 2;
  constexpr int WGM = 8 / WGN;
  constexpr int WROWS = BM / WGM;     // 64 or 32
  constexpr int MI = WROWS / 16;      // 4 or 2
  constexpr int BC = (BN == 128) ? 136 : 72;

  __shared__ bf16 As[2][2][BM][24];
  __shared__ bf16 Bs[2][2][16][BC];

  const int m0 = blockIdx.y * BM;
  const int n0 = blockIdx.x * BN;
  if (CM == 1 && n0 >= m0 + BM) return;

  int z  = blockIdx.z;
  int zb = z / NH, zh = z % NH;
  A += (long)zb*sA1 + (long)zh*sA2;
  if (PLB) { Bph += (long)zb*sB1 + (long)zh*sB2; Bpl += (long)zb*sB1 + (long)zh*sB2; }
  else       B   += (long)zb*sB1 + (long)zh*sB2;
  C += (long)zb*sC1 + (long)zh*sC2;

  const int tid = threadIdx.x;
  const int warp = tid >> 5, lane = tid & 31;
  const int wm = warp / WGN, wn = warp % WGN;
  const int lrow = lane & 15;
  const int lcol = (lane >> 4) << 3;

  // loader indices
  const int arow = tid >> 2;          // 0..63
  const int akc  = (tid & 3) << 2;
  const int bk   = tid >> 5;          // NN fp32 BN=128
  const int bc   = (tid & 31) << 2;
  const int bk2  = tid >> 4;          // NN fp32 BN=64
  const int bc2  = (tid & 15) << 2;
  const int brow = tid >> 4;          // NN plane BN=128: 0..15
  const int bc8  = (tid & 15) << 3;   // 0..120
  const int tn   = tid & 127;         // TRANSB
  const int tkh  = (tid >> 7) << 3;   // 0 or 8

  float4 pA0, pA1, pB0, pB1;
  uint4 u4h, u4l;

#define PREF_A(kt) { \
    pA0 = *(const float4*)&A[(long)(m0+arow)*lda + (kt) + akc]; \
    if (BM == 128) pA1 = *(const float4*)&A[(long)(m0+arow+64)*lda + (kt) + akc]; }

#define STORE_A(bf) { \
    unsigned h_, l_; \
    split2(pA0.x,pA0.y,h_,l_); *(unsigned*)&As[bf][0][arow][akc]=h_;   *(unsigned*)&As[bf][1][arow][akc]=l_; \
    split2(pA0.z,pA0.w,h_,l_); *(unsigned*)&As[bf][0][arow][akc+2]=h_; *(unsigned*)&As[bf][1][arow][akc+2]=l_; \
    if (BM == 128) { \
      split2(pA1.x,pA1.y,h_,l_); *(unsigned*)&As[bf][0][arow+64][akc]=h_;   *(unsigned*)&As[bf][1][arow+64][akc]=l_; \
      split2(pA1.z,pA1.w,h_,l_); *(unsigned*)&As[bf][0][arow+64][akc+2]=h_; *(unsigned*)&As[bf][1][arow+64][akc+2]=l_; } }

#define PREF_B(kt) { \
    if (PLB) { \
      if (TRANSB) { \
        if (n0 + tn < N) { \
          u4h = *(const uint4*)&Bph[(long)(n0+tn)*ldb + (kt) + tkh]; \
          u4l = *(const uint4*)&Bpl[(long)(n0+tn)*ldb + (kt) + tkh]; \
        } else { u4h = make_uint4(0,0,0,0); u4l = u4h; } \
      } else { \
        u4h = *(const uint4*)&Bph[(long)((kt)+brow)*ldb + n0 + bc8]; \
        u4l = *(const uint4*)&Bpl[(long)((kt)+brow)*ldb + n0 + bc8]; \
      } \
    } else if (TRANSB) { \
      if (n0 + tn < N) { \
        pB0 = *(const float4*)&B[(long)(n0+tn)*ldb + (kt) + tkh]; \
        pB1 = *(const float4*)&B[(long)(n0+tn)*ldb + (kt) + tkh + 4]; \
      } else { pB0 = make_float4(0.f,0.f,0.f,0.f); pB1 = pB0; } \
    } else if (BN == 128) { \
      pB0 = *(const float4*)&B[(long)((kt)+bk)*ldb + n0 + bc]; \
      pB1 = *(const float4*)&B[(long)((kt)+bk+8)*ldb + n0 + bc]; \
    } else { \
      pB0 = *(const float4*)&B[(long)((kt)+bk2)*ldb + n0 + bc2]; \
    } }

#define STORE_B(bf) { \
    if (PLB) { \
      if (TRANSB) { \
        const bf16* ph_ = (const bf16*)&u4h; \
        const bf16* pl_ = (const bf16*)&u4l; \
        _Pragma("unroll") \
        for (int i_=0;i_<8;i_++){ \
          Bs[bf][0][tkh+i_][tn] = ph_[i_]; \
          Bs[bf][1][tkh+i_][tn] = pl_[i_]; } \
      } else { \
        *(uint4*)&Bs[bf][0][brow][bc8] = u4h; \
        *(uint4*)&Bs[bf][1][brow][bc8] = u4l; \
      } \
    } else if (TRANSB) { \
      float v_[8] = {pB0.x,pB0.y,pB0.z,pB0.w,pB1.x,pB1.y,pB1.z,pB1.w}; \
      _Pragma("unroll") \
      for (int i_=0;i_<8;i_++){ \
        bf16 hh_ = __float2bfloat16_rn(v_[i_]); \
        Bs[bf][0][tkh+i_][tn] = hh_; \
        Bs[bf][1][tkh+i_][tn] = __float2bfloat16_rn(v_[i_] - __bfloat162float(hh_)); } \
    } else if (BN == 128) { \
      unsigned h_, l_; \
      split2(pB0.x,pB0.y,h_,l_); *(unsigned*)&Bs[bf][0][bk][bc]=h_;     *(unsigned*)&Bs[bf][1][bk][bc]=l_; \
      split2(pB0.z,pB0.w,h_,l_); *(unsigned*)&Bs[bf][0][bk][bc+2]=h_;   *(unsigned*)&Bs[bf][1][bk][bc+2]=l_; \
      split2(pB1.x,pB1.y,h_,l_); *(unsigned*)&Bs[bf][0][bk+8][bc]=h_;   *(unsigned*)&Bs[bf][1][bk+8][bc]=l_; \
      split2(pB1.z,pB1.w,h_,l_); *(unsigned*)&Bs[bf][0][bk+8][bc+2]=h_; *(unsigned*)&Bs[bf][1][bk+8][bc+2]=l_; \
    } else { \
      unsigned h_, l_; \
      split2(pB0.x,pB0.y,h_,l_); *(unsigned*)&Bs[bf][0][bk2][bc2]=h_;   *(unsigned*)&Bs[bf][1][bk2][bc2]=l_; \
      split2(pB0.z,pB0.w,h_,l_); *(unsigned*)&Bs[bf][0][bk2][bc2+2]=h_; *(unsigned*)&Bs[bf][1][bk2][bc2+2]=l_; } }

  float acc[MI][4][4];
#pragma unroll
  for (int i=0;i<MI;i++)
#pragma unroll
    for (int j=0;j<4;j++)
#pragma unroll
      for (int r=0;r<4;r++) acc[i][j][r]=0.f;

  int Keff = (CM == 2) ? ((m0 + BM < K) ? m0 + BM : K) : K;
  const int NT = Keff >> 4;

  PREF_A(0); PREF_B(0);
  STORE_A(0); STORE_B(0);
  __syncthreads();

  for (int it = 0; it < NT; ++it) {
    const int bf = it & 1;
    const bool more = (it + 1) < NT;
    if (more) { PREF_A((it+1)<<4); PREF_B((it+1)<<4); }

    unsigned Ah[MI][4], Al[MI][4], Bh[4][2], Bl[4][2];
#pragma unroll
    for (int mi=0; mi<MI; mi++){
      ldsm4(Ah[mi], &As[bf][0][wm*WROWS + mi*16 + lrow][lcol]);
      ldsm4(Al[mi], &As[bf][1][wm*WROWS + mi*16 + lrow][lcol]);
    }
#pragma unroll
    for (int np=0; np<2; np++){
      ldsm4t(Bh[2*np][0],Bh[2*np][1],Bh[2*np+1][0],Bh[2*np+1][1],
             &Bs[bf][0][lrow][wn*32 + np*16 + lcol]);
      ldsm4t(Bl[2*np][0],Bl[2*np][1],Bl[2*np+1][0],Bl[2*np+1][1],
             &Bs[bf][1][lrow][wn*32 + np*16 + lcol]);
    }
#pragma unroll
    for (int mi=0; mi<MI; mi++)
#pragma unroll
      for (int ni=0; ni<4; ni++){
        mma16816(acc[mi][ni], Ah[mi], Bh[ni]);
        mma16816(acc[mi][ni], Al[mi], Bh[ni]);
        mma16816(acc[mi][ni], Ah[mi], Bl[ni]);
      }

    if (more) { STORE_A(!bf); STORE_B(!bf); }
    __syncthreads();
  }

  // ---- epilogue ----
  const int rb = m0 + wm*WROWS + (lane >> 2);
  const int cb = n0 + wn*32 + 2*(lane & 3);
#pragma unroll
  for (int mi=0; mi<MI; mi++){
#pragma unroll
    for (int ni=0; ni<4; ni++){
      int c0 = cb + ni*8;
#pragma unroll
      for (int r=0; r<4; r++){
        int row = rb + mi*16 + ((r>>1)<<3);
        int col = c0 + (r&1);
        if (col >= N) continue;
        float v = acc[mi][ni][r];
        long idx = (long)row*ldc + col;
        if (EPI == 0) C[idx] = alpha * v;
        else if (EPI == 2) C[idx] = C[idx] + v + bias[col];
        else { v += bias[col]; C[idx] = 0.5f*v*(1.f + erff(v*0.70710678118654752f)); }
      }
    }
  }
#undef PREF_A
#undef STORE_A
#undef PREF_B
#undef STORE_B
}

// ---------------- host ----------------
extern "C" void kernel_launch(void* const* d_in, const int* in_sizes, int n_in,
                              void* d_out, int out_size) {
  const int*   idx  = (const int*  )d_in[0];
  const float* tokW = (const float*)d_in[1];
  const float* posW = (const float*)d_in[2];
  const float* ln1g = (const float*)d_in[3];
  const float* ln1b = (const float*)d_in[4];
  const float* Wq   = (const float*)d_in[5];
  const float* Wk   = (const float*)d_in[6];
  const float* Wv   = (const float*)d_in[7];
  const float* Wo   = (const float*)d_in[8];
  const float* bo   = (const float*)d_in[9];
  const float* ln2g = (const float*)d_in[10];
  const float* ln2b = (const float*)d_in[11];
  const float* W1   = (const float*)d_in[12];
  const float* b1   = (const float*)d_in[13];
  const float* W2   = (const float*)d_in[14];
  const float* b2   = (const float*)d_in[15];
  const float* lnfg = (const float*)d_in[16];
  const float* lnfb = (const float*)d_in[17];
  float* out = (float*)d_out;

  float *x,*h,*qkv,*att,*ff,*sc;
  bf16 *wch,*wcl,*woh,*wol,*w1h,*w1l,*w2h,*w2l,*tkh,*tkl;
  cudaGetSymbolAddress((void**)&x,   g_x);
  cudaGetSymbolAddress((void**)&h,   g_h);
  cudaGetSymbolAddress((void**)&qkv, g_qkv);
  cudaGetSymbolAddress((void**)&att, g_att);
  cudaGetSymbolAddress((void**)&ff,  g_ff);
  cudaGetSymbolAddress((void**)&sc,  g_sc);
  cudaGetSymbolAddress((void**)&wch, g_wch); cudaGetSymbolAddress((void**)&wcl, g_wcl);
  cudaGetSymbolAddress((void**)&woh, g_woh); cudaGetSymbolAddress((void**)&wol, g_wol);
  cudaGetSymbolAddress((void**)&w1h, g_w1h); cudaGetSymbolAddress((void**)&w1l, g_w1l);
  cudaGetSymbolAddress((void**)&w2h, g_w2h); cudaGetSymbolAddress((void**)&w2l, g_w2l);
  cudaGetSymbolAddress((void**)&tkh, g_tkh); cudaGetSymbolAddress((void**)&tkl, g_tkl);

  // ---- weight preconversion ----
  split_qkv<<<4096,256>>>(Wq, Wk, Wv, (uint2*)wch, (uint2*)wcl);
  split_w<<<2048,256>>>((const float4*)Wo, (uint2*)woh, (uint2*)wol, (long)NL*DD*DD/4);
  split_w<<<4096,256>>>((const float4*)W1, (uint2*)w1h, (uint2*)w1l, (long)NL*DD*FF/4);
  split_w<<<4096,256>>>((const float4*)W2, (uint2*)w2h, (uint2*)w2l, (long)NL*DD*FF/4);
  split_w<<<8192,256>>>((const float4*)tokW, (uint2*)tkh, (uint2*)tkl, (long)VV*DD/4);

  embed_kernel<<<BT,256>>>(idx, tokW, posW, x);

  const dim3 gQKV(3*DD/128, BT/128, 1);        // 384 CTAs
  const dim3 gD64(DD/128,   BT/64,  1);        // 256 CTAs
  const dim3 gFF (FF/128,   BT/128, 1);        // 512 CTAs
  const dim3 gSC (TT/128,   TT/128, BB*NH);
  const dim3 gAV (1,        TT/128, BB*NH);
  const dim3 gLM ((VV+127)/128, BT/128, 1);
  const long sD3  = (long)DD*3*DD;
  const long sDD2 = (long)DD*DD;
  const long sDF  = (long)DD*FF;

  for (int l = 0; l < NL; l++) {
    long lDD = (long)l*DD, lF = (long)l*FF;

    ln_kernel<<<BT,256>>>(x, h, ln1g + lDD, ln1b + lDD);

    // fused QKV: qkv[BT,3D] = h @ Wcat[l]   (plane B)
    bgemm<128,128,false,true,0,0><<<gQKV,256>>>(BT, 3*DD, DD, 1.f,
        h, DD,0,0,  nullptr, wch + l*sD3, wcl + l*sD3, 3*DD,0,0,
        qkv, 3*DD,0,0, nullptr);

    // scores = 0.125 * q @ k^T  (fp32 B, causal tile skip)
    bgemm<128,128,true,false,0,1><<<gSC,256>>>(TT, TT, HDIM, 0.125f,
        qkv,      3*DD, (long)TT*3*DD, HDIM,
        qkv + DD, nullptr, nullptr, 3*DD, (long)TT*3*DD, HDIM,
        sc, TT, (long)NH*TT*TT, (long)TT*TT, nullptr);

    softmax_kernel<<<dim3(TT, BB*NH), 256>>>(sc);

    // att = P @ v  (fp32 B, causal K limit)
    bgemm<128,64,false,false,0,2><<<gAV,256>>>(TT, HDIM, TT, 1.f,
        sc,         TT, (long)NH*TT*TT, (long)TT*TT,
        qkv + 2*DD, nullptr, nullptr, 3*DD, (long)TT*3*DD, HDIM,
        att, DD, (long)TT*DD, HDIM, nullptr);

    // x += att @ Wo + bo   (plane B)
    bgemm<64,128,false,true,2,0><<<gD64,256>>>(BT, DD, DD, 1.f,
        att, DD,0,0,  nullptr, woh + l*sDD2, wol + l*sDD2, DD,0,0,
        x, DD,0,0, bo + lDD);

    ln_kernel<<<BT,256>>>(x, h, ln2g + lDD, ln2b + lDD);

    // ff = gelu(h @ W1 + b1)   (plane B)
    bgemm<128,128,false,true,3,0><<<gFF,256>>>(BT, FF, DD, 1.f,
        h, DD,0,0,  nullptr, w1h + l*sDF, w1l + l*sDF, FF,0,0,
        ff, FF,0,0, b1 + lF);

    // x += ff @ W2 + b2   (plane B)
    bgemm<64,128,false,true,2,0><<<gD64,256>>>(BT, DD, FF, 1.f,
        ff, FF,0,0,  nullptr, w2h + l*sDF, w2l + l*sDF, DD,0,0,
        x, DD,0,0, b2 + lDD);
  }

  ln_kernel<<<BT,256>>>(x, h, lnfg, lnfb);

  // logits = h @ tokW^T  (plane B, TRANSB)
  bgemm<128,128,true,true,0,0><<<gLM,256>>>(BT, VV, DD, 1.f,
      h, DD,0,0,  nullptr, tkh, tkl, DD,0,0,
      out, VV,0,0, nullptr);
}